// round 2
// baseline (speedup 1.0000x reference)
#include <cuda_runtime.h>
#include <cstdint>

#define NUM_HEADS 32
#define KV_HEADS  8
#define SEQ       2048
#define HD        128
#define BM        64
#define BN        64

// shared memory word strides (chosen for conflict-free MMA B-fragment reads)
#define QSTRIDE 132
#define KSTRIDE 132
#define VSTRIDE 136
#define SK_OFF  34816                       // bytes: region0 = max(64*528, 64*544)
#define SMEM_TOTAL (34816 + 64 * KSTRIDE * 4)   // 68608 bytes

__device__ __forceinline__ float fast_exp2(float x) {
    float y; asm("ex2.approx.f32 %0, %1;" : "=f"(y) : "f"(x)); return y;
}
__device__ __forceinline__ float fast_rcp(float x) {
    float y; asm("rcp.approx.f32 %0, %1;" : "=f"(y) : "f"(x)); return y;
}
__device__ __forceinline__ uint32_t f2tf(float f) {
    uint32_t u; asm("cvt.rna.tf32.f32 %0, %1;" : "=r"(u) : "f"(f)); return u;
}
__device__ __forceinline__ void mma_tf32(float* c, const uint32_t* a, uint32_t b0, uint32_t b1) {
    asm volatile(
        "mma.sync.aligned.m16n8k8.row.col.f32.tf32.tf32.f32 "
        "{%0,%1,%2,%3}, {%4,%5,%6,%7}, {%8,%9}, {%0,%1,%2,%3};"
        : "+f"(c[0]), "+f"(c[1]), "+f"(c[2]), "+f"(c[3])
        : "r"(a[0]), "r"(a[1]), "r"(a[2]), "r"(a[3]), "r"(b0), "r"(b1));
}

__global__ void __launch_bounds__(128)
fa_kernel(const float* __restrict__ Q, const float* __restrict__ K,
          const float* __restrict__ V, float* __restrict__ Out)
{
    const int qt   = blockIdx.x;
    const int h    = blockIdx.y;
    const int b    = blockIdx.z;
    const int kvh  = h >> 2;
    const int tid  = threadIdx.x;
    const int w    = tid >> 5;
    const int lane = tid & 31;
    const int g    = lane >> 2;
    const int tg   = lane & 3;

    const float SCALE   = 0.08838834764831845f;   // 128^-0.5
    const float SOFTCAP = 50.0f;
    const float INV_CAP = 0.02f;
    const float LOG2E   = 1.4426950408889634f;

    extern __shared__ __align__(16) unsigned char smem[];
    uint32_t* sQV = (uint32_t*)smem;             // Q (stride 132w) then V (stride 136w)
    uint32_t* sK  = (uint32_t*)(smem + SK_OFF);  // stride 132w

    // ---------------- Q: gmem -> smem as tf32 (pre-scaled) ----------------
    const float* Qbase = Q + (((size_t)(b * NUM_HEADS + h)) * SEQ + (size_t)qt * BM) * HD;
    #pragma unroll
    for (int i = 0; i < 16; i++) {
        int idx = tid + i * 128;
        int r = idx >> 5, c4 = (idx & 31) << 2;
        float4 v = *(const float4*)(Qbase + r * HD + c4);
        uint4 u = make_uint4(f2tf(v.x * SCALE), f2tf(v.y * SCALE),
                             f2tf(v.z * SCALE), f2tf(v.w * SCALE));
        *(uint4*)(sQV + r * QSTRIDE + c4) = u;
    }
    __syncthreads();

    // Q A-fragments (m16n8k8): 16 k-chunks of 8 dims
    uint32_t qf[16][4];
    {
        int r0 = w * 16 + g;
        const uint32_t* q0 = sQV + r0 * QSTRIDE;
        const uint32_t* q1 = sQV + (r0 + 8) * QSTRIDE;
        #pragma unroll
        for (int kc = 0; kc < 16; kc++) {
            int d0 = kc * 8 + tg;
            qf[kc][0] = q0[d0];
            qf[kc][1] = q1[d0];
            qf[kc][2] = q0[d0 + 4];
            qf[kc][3] = q1[d0 + 4];
        }
    }

    float o[16][4];
    #pragma unroll
    for (int j = 0; j < 16; j++) { o[j][0] = o[j][1] = o[j][2] = o[j][3] = 0.f; }
    float m0 = -INFINITY, m1 = -INFINITY;
    float l0 = 0.f, l1 = 0.f;

    const float* Kb = K + ((size_t)(b * KV_HEADS + kvh)) * SEQ * HD;
    const float* Vb = V + ((size_t)(b * KV_HEADS + kvh)) * SEQ * HD;
    const int r0g = qt * BM + w * 16 + g;

    for (int kt = 0; kt <= qt; kt++) {
        __syncthreads();   // previous tile fully consumed (also protects sQ on iter 0)

        // ---- K tile -> smem tf32, row-major [key][dim], stride 132w ----
        const float* Kt = Kb + (size_t)kt * BN * HD;
        #pragma unroll
        for (int i = 0; i < 16; i++) {
            int idx = tid + i * 128;
            int r = idx >> 5, c4 = (idx & 31) << 2;
            float4 v = *(const float4*)(Kt + r * HD + c4);
            *(uint4*)(sK + r * KSTRIDE + c4) =
                make_uint4(f2tf(v.x), f2tf(v.y), f2tf(v.z), f2tf(v.w));
        }
        // ---- V tile -> smem tf32, row-major [key][dim], stride 136w ----
        const float* Vt = Vb + (size_t)kt * BN * HD;
        #pragma unroll
        for (int i = 0; i < 16; i++) {
            int idx = tid + i * 128;
            int r = idx >> 5, c4 = (idx & 31) << 2;
            float4 v = *(const float4*)(Vt + r * HD + c4);
            *(uint4*)(sQV + r * VSTRIDE + c4) =
                make_uint4(f2tf(v.x), f2tf(v.y), f2tf(v.z), f2tf(v.w));
        }
        __syncthreads();

        // ---- S = (Q*scale) K^T ----
        float s[8][4];
        #pragma unroll
        for (int j = 0; j < 8; j++) { s[j][0] = s[j][1] = s[j][2] = s[j][3] = 0.f; }
        #pragma unroll
        for (int j = 0; j < 8; j++) {
            const uint32_t* kr = sK + (j * 8 + g) * KSTRIDE;
            #pragma unroll
            for (int kc = 0; kc < 16; kc++) {
                int d0 = kc * 8 + tg;
                mma_tf32(s[j], qf[kc], kr[d0], kr[d0 + 4]);
            }
        }

        // ---- exact softcap (tanh via exp) + causal mask ----
        const bool diag = (kt == qt);
        #pragma unroll
        for (int j = 0; j < 8; j++) {
            #pragma unroll
            for (int q = 0; q < 4; q++) {
                float xs = s[j][q] * INV_CAP;
                float z  = fast_exp2(xs * (2.0f * LOG2E));   // e^{2x}
                float t  = 1.0f - 2.0f * fast_rcp(z + 1.0f); // tanh(x)
                float x  = SOFTCAP * t;
                if (diag) {
                    int col = kt * BN + j * 8 + tg * 2 + (q & 1);
                    int row = r0g + ((q >= 2) ? 8 : 0);
                    if (col > row) x += -1e9f;
                }
                s[j][q] = x;
            }
        }

        // ---- online softmax ----
        float mx0 = -INFINITY, mx1 = -INFINITY;
        #pragma unroll
        for (int j = 0; j < 8; j++) {
            mx0 = fmaxf(mx0, fmaxf(s[j][0], s[j][1]));
            mx1 = fmaxf(mx1, fmaxf(s[j][2], s[j][3]));
        }
        mx0 = fmaxf(mx0, __shfl_xor_sync(0xffffffffu, mx0, 1));
        mx0 = fmaxf(mx0, __shfl_xor_sync(0xffffffffu, mx0, 2));
        mx1 = fmaxf(mx1, __shfl_xor_sync(0xffffffffu, mx1, 1));
        mx1 = fmaxf(mx1, __shfl_xor_sync(0xffffffffu, mx1, 2));

        float mn0 = fmaxf(m0, mx0), mn1 = fmaxf(m1, mx1);
        float a0 = fast_exp2((m0 - mn0) * LOG2E);
        float a1 = fast_exp2((m1 - mn1) * LOG2E);
        m0 = mn0; m1 = mn1;

        float sum0 = 0.f, sum1 = 0.f;
        #pragma unroll
        for (int j = 0; j < 8; j++) {
            s[j][0] = fast_exp2((s[j][0] - mn0) * LOG2E);
            s[j][1] = fast_exp2((s[j][1] - mn0) * LOG2E);
            s[j][2] = fast_exp2((s[j][2] - mn1) * LOG2E);
            s[j][3] = fast_exp2((s[j][3] - mn1) * LOG2E);
            sum0 += s[j][0] + s[j][1];
            sum1 += s[j][2] + s[j][3];
        }
        sum0 += __shfl_xor_sync(0xffffffffu, sum0, 1);
        sum0 += __shfl_xor_sync(0xffffffffu, sum0, 2);
        sum1 += __shfl_xor_sync(0xffffffffu, sum1, 1);
        sum1 += __shfl_xor_sync(0xffffffffu, sum1, 2);
        l0 = l0 * a0 + sum0;
        l1 = l1 * a1 + sum1;

        #pragma unroll
        for (int j = 0; j < 16; j++) {
            o[j][0] *= a0; o[j][1] *= a0; o[j][2] *= a1; o[j][3] *= a1;
        }

        // ---- O += P V ----
        const int src0 = (lane & 28) | (tg >> 1);
        const bool odd = tg & 1;
        #pragma unroll
        for (int kc = 0; kc < 8; kc++) {
            // permute S-accumulator layout (cols 2tg,2tg+1) -> A-frag layout (cols tg, tg+4)
            float v00 = __shfl_sync(0xffffffffu, s[kc][0], src0);
            float v01 = __shfl_sync(0xffffffffu, s[kc][1], src0);
            float v10 = __shfl_sync(0xffffffffu, s[kc][0], src0 + 2);
            float v11 = __shfl_sync(0xffffffffu, s[kc][1], src0 + 2);
            float w00 = __shfl_sync(0xffffffffu, s[kc][2], src0);
            float w01 = __shfl_sync(0xffffffffu, s[kc][3], src0);
            float w10 = __shfl_sync(0xffffffffu, s[kc][2], src0 + 2);
            float w11 = __shfl_sync(0xffffffffu, s[kc][3], src0 + 2);
            uint32_t pa[4];
            pa[0] = f2tf(odd ? v01 : v00);
            pa[1] = f2tf(odd ? w01 : w00);
            pa[2] = f2tf(odd ? v11 : v10);
            pa[3] = f2tf(odd ? w11 : w10);

            const uint32_t* vr0 = sQV + (kc * 8 + tg) * VSTRIDE;
            const uint32_t* vr1 = sQV + (kc * 8 + tg + 4) * VSTRIDE;
            #pragma unroll
            for (int jd = 0; jd < 16; jd++) {
                int d0 = jd * 8 + g;
                mma_tf32(o[jd], pa, vr0[d0], vr1[d0]);
            }
        }
    }

    // ---------------- epilogue: normalize + write [B, q, H*D] ----------------
    float inv0 = 1.f / l0, inv1 = 1.f / l1;
    float* Ob = Out + (size_t)b * SEQ * (NUM_HEADS * HD) + (size_t)h * HD;
    #pragma unroll
    for (int jd = 0; jd < 16; jd++) {
        int d0 = jd * 8 + tg * 2;
        float2 v0 = make_float2(o[jd][0] * inv0, o[jd][1] * inv0);
        float2 v1 = make_float2(o[jd][2] * inv1, o[jd][3] * inv1);
        *(float2*)(Ob + (size_t)r0g * (NUM_HEADS * HD) + d0)       = v0;
        *(float2*)(Ob + (size_t)(r0g + 8) * (NUM_HEADS * HD) + d0) = v1;
    }
}

extern "C" void kernel_launch(void* const* d_in, const int* in_sizes, int n_in,
                              void* d_out, int out_size)
{
    const float* Q = (const float*)d_in[0];
    const float* K = (const float*)d_in[1];
    const float* V = (const float*)d_in[2];
    float* Out = (float*)d_out;

    int B = in_sizes[0] / (NUM_HEADS * SEQ * HD);
    cudaFuncSetAttribute(fa_kernel, cudaFuncAttributeMaxDynamicSharedMemorySize, SMEM_TOTAL);
    dim3 grid(SEQ / BM, NUM_HEADS, B);
    fa_kernel<<<grid, 128, SMEM_TOTAL>>>(Q, K, V, Out);
}

// round 3
// speedup vs baseline: 1.0853x; 1.0853x over previous
#include <cuda_runtime.h>
#include <cstdint>

#define NUM_HEADS 32
#define KV_HEADS  8
#define SEQ       2048
#define HD        128
#define BM        128
#define BN        64
#define NTHREADS  256

// shared memory word strides (conflict-free MMA B-fragment reads)
#define QSTRIDE 132
#define KSTRIDE 132
#define VSTRIDE 136
#define SK_OFF  67584                            // bytes: 128*132*4 (Q region, reused for V)
#define SMEM_TOTAL (67584 + 64 * KSTRIDE * 4)    // 101376 bytes

__device__ __forceinline__ float fast_exp2(float x) {
    float y; asm("ex2.approx.f32 %0, %1;" : "=f"(y) : "f"(x)); return y;
}
__device__ __forceinline__ float fast_rcp(float x) {
    float y; asm("rcp.approx.f32 %0, %1;" : "=f"(y) : "f"(x)); return y;
}
__device__ __forceinline__ uint32_t f2tf(float f) {
    uint32_t u; asm("cvt.rna.tf32.f32 %0, %1;" : "=r"(u) : "f"(f)); return u;
}
__device__ __forceinline__ void mma_tf32(float* c, const uint32_t* a, uint32_t b0, uint32_t b1) {
    asm volatile(
        "mma.sync.aligned.m16n8k8.row.col.f32.tf32.tf32.f32 "
        "{%0,%1,%2,%3}, {%4,%5,%6,%7}, {%8,%9}, {%0,%1,%2,%3};"
        : "+f"(c[0]), "+f"(c[1]), "+f"(c[2]), "+f"(c[3])
        : "r"(a[0]), "r"(a[1]), "r"(a[2]), "r"(a[3]), "r"(b0), "r"(b1));
}

__global__ void __launch_bounds__(NTHREADS)
fa_kernel(const float* __restrict__ Q, const float* __restrict__ K,
          const float* __restrict__ V, float* __restrict__ Out)
{
    const int qt   = blockIdx.x;
    const int h    = blockIdx.y;
    const int b    = blockIdx.z;
    const int kvh  = h >> 2;
    const int tid  = threadIdx.x;
    const int w    = tid >> 5;
    const int lane = tid & 31;
    const int g    = lane >> 2;
    const int tg   = lane & 3;

    const float SCALE      = 0.08838834764831845f;    // 128^-0.5
    const float TANH_ARG   = 0.057707801635558534f;   // 2*log2e/50
    const float CAP_L2E    = 72.13475204444817f;      // 50*log2e
    const float CAP_L2E_N2 = -144.26950408889634f;    // -2*50*log2e

    extern __shared__ __align__(16) unsigned char smem[];
    uint32_t* sQV = (uint32_t*)smem;             // Q (128 rows, stride 132w), reused for V (stride 136w)
    uint32_t* sK  = (uint32_t*)(smem + SK_OFF);  // K (64 rows, stride 132w)

    // ---------------- Q: gmem -> smem as tf32 (pre-scaled) ----------------
    const float* Qbase = Q + (((size_t)(b * NUM_HEADS + h)) * SEQ + (size_t)qt * BM) * HD;
    #pragma unroll
    for (int i = 0; i < 16; i++) {
        int idx = tid + i * NTHREADS;
        int r = idx >> 5, c4 = (idx & 31) << 2;
        float4 v = *(const float4*)(Qbase + r * HD + c4);
        *(uint4*)(sQV + r * QSTRIDE + c4) =
            make_uint4(f2tf(v.x * SCALE), f2tf(v.y * SCALE),
                       f2tf(v.z * SCALE), f2tf(v.w * SCALE));
    }
    __syncthreads();

    // Q A-fragments (m16n8k8): 16 k-chunks of 8 dims
    uint32_t qf[16][4];
    {
        int r0 = w * 16 + g;
        const uint32_t* q0 = sQV + r0 * QSTRIDE;
        const uint32_t* q1 = sQV + (r0 + 8) * QSTRIDE;
        #pragma unroll
        for (int kc = 0; kc < 16; kc++) {
            int d0 = kc * 8 + tg;
            qf[kc][0] = q0[d0];
            qf[kc][1] = q1[d0];
            qf[kc][2] = q0[d0 + 4];
            qf[kc][3] = q1[d0 + 4];
        }
    }

    float o[16][4];
    #pragma unroll
    for (int j = 0; j < 16; j++) { o[j][0] = o[j][1] = o[j][2] = o[j][3] = 0.f; }
    float m0 = -INFINITY, m1 = -INFINITY;   // running max in log2 domain
    float l0 = 0.f, l1 = 0.f;

    const float* Kb = K + ((size_t)(b * KV_HEADS + kvh)) * SEQ * HD;
    const float* Vb = V + ((size_t)(b * KV_HEADS + kvh)) * SEQ * HD;
    const int r0g     = qt * BM + w * 16 + g;   // query row for regs [0],[1] ([2],[3] = +8)
    const int row_min = qt * BM + w * 16;       // warp-uniform
    const int row_max = row_min + 15;

    const int ktmax = 2 * qt + 1;
    for (int kt = 0; kt <= ktmax; kt++) {
        __syncthreads();   // previous tile fully consumed (also protects sQ on iter 0)

        // ---- K tile -> smem tf32, row-major [key][dim] ----
        const float* Kt = Kb + (size_t)kt * BN * HD;
        #pragma unroll
        for (int i = 0; i < 8; i++) {
            int idx = tid + i * NTHREADS;
            int r = idx >> 5, c4 = (idx & 31) << 2;
            float4 v = *(const float4*)(Kt + r * HD + c4);
            *(uint4*)(sK + r * KSTRIDE + c4) =
                make_uint4(f2tf(v.x), f2tf(v.y), f2tf(v.z), f2tf(v.w));
        }
        // ---- V tile -> smem tf32, row-major [key][dim] ----
        const float* Vt = Vb + (size_t)kt * BN * HD;
        #pragma unroll
        for (int i = 0; i < 8; i++) {
            int idx = tid + i * NTHREADS;
            int r = idx >> 5, c4 = (idx & 31) << 2;
            float4 v = *(const float4*)(Vt + r * HD + c4);
            *(uint4*)(sQV + r * VSTRIDE + c4) =
                make_uint4(f2tf(v.x), f2tf(v.y), f2tf(v.z), f2tf(v.w));
        }
        __syncthreads();

        if (kt * BN > row_max) continue;   // tile fully above diagonal for this warp

        // ---- S = (Q*scale) K^T ----
        float s[8][4];
        #pragma unroll
        for (int j = 0; j < 8; j++) { s[j][0] = s[j][1] = s[j][2] = s[j][3] = 0.f; }
        #pragma unroll
        for (int j = 0; j < 8; j++) {
            const uint32_t* kr = sK + (j * 8 + g) * KSTRIDE;
            #pragma unroll
            for (int kc = 0; kc < 16; kc++) {
                int d0 = kc * 8 + tg;
                mma_tf32(s[j], qf[kc], kr[d0], kr[d0 + 4]);
            }
        }

        // ---- exact softcap -> log2 domain + causal mask ----
        const bool diag = (kt * BN + BN - 1 > row_min);
        #pragma unroll
        for (int j = 0; j < 8; j++) {
            #pragma unroll
            for (int q = 0; q < 4; q++) {
                float z = fast_exp2(s[j][q] * TANH_ARG);          // e^{2x/50}
                // 50*tanh(x/50)*log2e == CAP_L2E + CAP_L2E_N2 / (z+1)
                float x = fmaf(CAP_L2E_N2, fast_rcp(z + 1.0f), CAP_L2E);
                if (diag) {
                    int col = kt * BN + j * 8 + tg * 2 + (q & 1);
                    int row = r0g + ((q >= 2) ? 8 : 0);
                    if (col > row) x = -1e9f;
                }
                s[j][q] = x;
            }
        }

        // ---- online softmax (log2 domain) ----
        float mx0 = -INFINITY, mx1 = -INFINITY;
        #pragma unroll
        for (int j = 0; j < 8; j++) {
            mx0 = fmaxf(mx0, fmaxf(s[j][0], s[j][1]));
            mx1 = fmaxf(mx1, fmaxf(s[j][2], s[j][3]));
        }
        mx0 = fmaxf(mx0, __shfl_xor_sync(0xffffffffu, mx0, 1));
        mx0 = fmaxf(mx0, __shfl_xor_sync(0xffffffffu, mx0, 2));
        mx1 = fmaxf(mx1, __shfl_xor_sync(0xffffffffu, mx1, 1));
        mx1 = fmaxf(mx1, __shfl_xor_sync(0xffffffffu, mx1, 2));

        float mn0 = fmaxf(m0, mx0), mn1 = fmaxf(m1, mx1);
        float a0 = fast_exp2(m0 - mn0);
        float a1 = fast_exp2(m1 - mn1);
        m0 = mn0; m1 = mn1;

        float sum0 = 0.f, sum1 = 0.f;
        #pragma unroll
        for (int j = 0; j < 8; j++) {
            s[j][0] = fast_exp2(s[j][0] - mn0);
            s[j][1] = fast_exp2(s[j][1] - mn0);
            s[j][2] = fast_exp2(s[j][2] - mn1);
            s[j][3] = fast_exp2(s[j][3] - mn1);
            sum0 += s[j][0] + s[j][1];
            sum1 += s[j][2] + s[j][3];
        }
        sum0 += __shfl_xor_sync(0xffffffffu, sum0, 1);
        sum0 += __shfl_xor_sync(0xffffffffu, sum0, 2);
        sum1 += __shfl_xor_sync(0xffffffffu, sum1, 1);
        sum1 += __shfl_xor_sync(0xffffffffu, sum1, 2);
        l0 = l0 * a0 + sum0;
        l1 = l1 * a1 + sum1;

        #pragma unroll
        for (int j = 0; j < 16; j++) {
            o[j][0] *= a0; o[j][1] *= a0; o[j][2] *= a1; o[j][3] *= a1;
        }

        // ---- O += P V ----
        const int src0 = (lane & 28) | (tg >> 1);
        const bool odd = tg & 1;
        #pragma unroll
        for (int kc = 0; kc < 8; kc++) {
            // permute S-accumulator layout (cols 2tg,2tg+1) -> A-frag layout (cols tg, tg+4)
            float v00 = __shfl_sync(0xffffffffu, s[kc][0], src0);
            float v01 = __shfl_sync(0xffffffffu, s[kc][1], src0);
            float v10 = __shfl_sync(0xffffffffu, s[kc][0], src0 + 2);
            float v11 = __shfl_sync(0xffffffffu, s[kc][1], src0 + 2);
            float w00 = __shfl_sync(0xffffffffu, s[kc][2], src0);
            float w01 = __shfl_sync(0xffffffffu, s[kc][3], src0);
            float w10 = __shfl_sync(0xffffffffu, s[kc][2], src0 + 2);
            float w11 = __shfl_sync(0xffffffffu, s[kc][3], src0 + 2);
            uint32_t pa[4];
            pa[0] = f2tf(odd ? v01 : v00);
            pa[1] = f2tf(odd ? w01 : w00);
            pa[2] = f2tf(odd ? v11 : v10);
            pa[3] = f2tf(odd ? w11 : w10);

            const uint32_t* vr0 = sQV + (kc * 8 + tg) * VSTRIDE;
            const uint32_t* vr1 = sQV + (kc * 8 + tg + 4) * VSTRIDE;
            #pragma unroll
            for (int jd = 0; jd < 16; jd++) {
                int d0 = jd * 8 + g;
                mma_tf32(o[jd], pa, vr0[d0], vr1[d0]);
            }
        }
    }

    // ---------------- epilogue: normalize + write [B, q, H*D] ----------------
    float inv0 = 1.f / l0, inv1 = 1.f / l1;
    float* Ob = Out + (size_t)b * SEQ * (NUM_HEADS * HD) + (size_t)h * HD;
    #pragma unroll
    for (int jd = 0; jd < 16; jd++) {
        int d0 = jd * 8 + tg * 2;
        float2 v0 = make_float2(o[jd][0] * inv0, o[jd][1] * inv0);
        float2 v1 = make_float2(o[jd][2] * inv1, o[jd][3] * inv1);
        *(float2*)(Ob + (size_t)r0g * (NUM_HEADS * HD) + d0)       = v0;
        *(float2*)(Ob + (size_t)(r0g + 8) * (NUM_HEADS * HD) + d0) = v1;
    }
}

extern "C" void kernel_launch(void* const* d_in, const int* in_sizes, int n_in,
                              void* d_out, int out_size)
{
    const float* Q = (const float*)d_in[0];
    const float* K = (const float*)d_in[1];
    const float* V = (const float*)d_in[2];
    float* Out = (float*)d_out;

    int B = in_sizes[0] / (NUM_HEADS * SEQ * HD);
    cudaFuncSetAttribute(fa_kernel, cudaFuncAttributeMaxDynamicSharedMemorySize, SMEM_TOTAL);
    dim3 grid(SEQ / BM, NUM_HEADS, B);
    fa_kernel<<<grid, NTHREADS, SMEM_TOTAL>>>(Q, K, V, Out);
}

// round 4
// speedup vs baseline: 1.1378x; 1.0483x over previous
#include <cuda_runtime.h>
#include <cstdint>

#define NUM_HEADS 32
#define KV_HEADS  8
#define SEQ       2048
#define HD        128
#define BM        128
#define BN        64
#define NTHREADS  256
#define MAXB      2

// smem word strides (conflict-free MMA B-fragment reads)
#define QSTRIDE 132
#define KSTRIDE 132
#define VSTRIDE 136
#define KSTAGE  (64 * KSTRIDE)            // 8448 words
#define VSTAGE  (64 * VSTRIDE)            // 8704 words
#define SV_OFF  (2 * KSTAGE)              // 16896 words
#define SMEM_WORDS (2 * KSTAGE + 2 * VSTAGE)   // 34304 words
#define SMEM_TOTAL (SMEM_WORDS * 4)            // 137216 bytes

// tf32-preconverted K/V scratch
__device__ uint32_t g_Ktf[MAXB * KV_HEADS * SEQ * HD];
__device__ uint32_t g_Vtf[MAXB * KV_HEADS * SEQ * HD];

__device__ __forceinline__ float fast_exp2(float x) {
    float y; asm("ex2.approx.f32 %0, %1;" : "=f"(y) : "f"(x)); return y;
}
__device__ __forceinline__ float fast_rcp(float x) {
    float y; asm("rcp.approx.f32 %0, %1;" : "=f"(y) : "f"(x)); return y;
}
__device__ __forceinline__ uint32_t f2tf(float f) {
    uint32_t u; asm("cvt.rna.tf32.f32 %0, %1;" : "=r"(u) : "f"(f)); return u;
}
__device__ __forceinline__ void mma_tf32(float* c, const uint32_t* a, uint32_t b0, uint32_t b1) {
    asm volatile(
        "mma.sync.aligned.m16n8k8.row.col.f32.tf32.tf32.f32 "
        "{%0,%1,%2,%3}, {%4,%5,%6,%7}, {%8,%9}, {%0,%1,%2,%3};"
        : "+f"(c[0]), "+f"(c[1]), "+f"(c[2]), "+f"(c[3])
        : "r"(a[0]), "r"(a[1]), "r"(a[2]), "r"(a[3]), "r"(b0), "r"(b1));
}
__device__ __forceinline__ void cp16(uint32_t dst_smem, const void* src) {
    asm volatile("cp.async.cg.shared.global [%0], [%1], 16;"
                 :: "r"(dst_smem), "l"(src));
}

// ---------------- pre-pass: f32 -> tf32 (rna) for K and V ----------------
__global__ void __launch_bounds__(256)
conv_kernel(const float* __restrict__ K, const float* __restrict__ V, int n4)
{
    int i = blockIdx.x * 256 + threadIdx.x;
    if (i < n4) {
        float4 k = *(const float4*)(K + i * 4);
        float4 v = *(const float4*)(V + i * 4);
        *(uint4*)(g_Ktf + i * 4) = make_uint4(f2tf(k.x), f2tf(k.y), f2tf(k.z), f2tf(k.w));
        *(uint4*)(g_Vtf + i * 4) = make_uint4(f2tf(v.x), f2tf(v.y), f2tf(v.z), f2tf(v.w));
    }
}

__global__ void __launch_bounds__(NTHREADS)
fa_kernel(const float* __restrict__ Q, float* __restrict__ Out)
{
    const int qt   = blockIdx.x;
    const int h    = blockIdx.y;
    const int b    = blockIdx.z;
    const int kvh  = h >> 2;
    const int tid  = threadIdx.x;
    const int w    = tid >> 5;
    const int lane = tid & 31;
    const int g    = lane >> 2;
    const int tg   = lane & 3;

    const float SCALE      = 0.08838834764831845f;    // 128^-0.5
    const float TANH_ARG   = 0.057707801635558534f;   // 2*log2e/50
    const float CAP_L2E    = 72.13475204444817f;      // 50*log2e
    const float CAP_L2E_N2 = -144.26950408889634f;    // -2*50*log2e

    extern __shared__ __align__(16) unsigned char smem[];
    uint32_t* sW = (uint32_t*)smem;   // [K0 | K1 | V0 | V1]
    uint32_t smem_u32;
    asm("{ .reg .u64 t; cvta.to.shared.u64 t, %1; cvt.u32.u64 %0, t; }"
        : "=r"(smem_u32) : "l"(smem));

    // ---------------- Q: gmem -> smem (K0+K1 region) as tf32, pre-scaled ----------------
    const float* Qbase = Q + (((size_t)(b * NUM_HEADS + h)) * SEQ + (size_t)qt * BM) * HD;
    #pragma unroll
    for (int i = 0; i < 16; i++) {
        int idx = tid + i * NTHREADS;
        int r = idx >> 5, c4 = (idx & 31) << 2;
        float4 v = *(const float4*)(Qbase + r * HD + c4);
        *(uint4*)(sW + r * QSTRIDE + c4) =
            make_uint4(f2tf(v.x * SCALE), f2tf(v.y * SCALE),
                       f2tf(v.z * SCALE), f2tf(v.w * SCALE));
    }
    __syncthreads();

    // Q A-fragments (m16n8k8): 16 k-chunks of 8 dims
    uint32_t qf[16][4];
    {
        int r0 = w * 16 + g;
        const uint32_t* q0 = sW + r0 * QSTRIDE;
        const uint32_t* q1 = sW + (r0 + 8) * QSTRIDE;
        #pragma unroll
        for (int kc = 0; kc < 16; kc++) {
            int d0 = kc * 8 + tg;
            qf[kc][0] = q0[d0];
            qf[kc][1] = q1[d0];
            qf[kc][2] = q0[d0 + 4];
            qf[kc][3] = q1[d0 + 4];
        }
    }
    __syncthreads();   // Q fully consumed; K0/K1 region free for cp.async

    float o[16][4];
    #pragma unroll
    for (int j = 0; j < 16; j++) { o[j][0] = o[j][1] = o[j][2] = o[j][3] = 0.f; }
    float m0 = -INFINITY, m1 = -INFINITY;
    float l0 = 0.f, l1 = 0.f;

    const uint32_t* Kb = g_Ktf + ((size_t)(b * KV_HEADS + kvh)) * SEQ * HD;
    const uint32_t* Vb = g_Vtf + ((size_t)(b * KV_HEADS + kvh)) * SEQ * HD;
    const int r0g     = qt * BM + w * 16 + g;
    const int row_min = qt * BM + w * 16;
    const int row_max = row_min + 15;
    const int ktmax   = 2 * qt + 1;

    // per-thread cp.async task: 8 chunks of 16B for K, 8 for V
    // chunk c (0..2047): row = c>>5, col quad = (c&31)*4
    const int c_row = tid >> 5;           // base row (tid-derived); iterate +8 rows
    const int c_col = (tid & 31) << 2;    // word offset within row (0..124)

    // ---- prefetch tile 0 into stage 0 ----
    {
        const uint32_t* Kt = Kb;
        const uint32_t* Vt = Vb;
        #pragma unroll
        for (int i = 0; i < 8; i++) {
            int r = c_row + i * 8;
            cp16(smem_u32 + (r * KSTRIDE + c_col) * 4, Kt + r * HD + c_col);
            cp16(smem_u32 + (SV_OFF + r * VSTRIDE + c_col) * 4, Vt + r * HD + c_col);
        }
        asm volatile("cp.async.commit_group;");
    }

    for (int kt = 0; kt <= ktmax; kt++) {
        const int cur = kt & 1;
        // ---- prefetch next tile into other stage (that stage's compute finished last iter) ----
        if (kt < ktmax) {
            const int nxt = cur ^ 1;
            const uint32_t* Kt = Kb + (size_t)(kt + 1) * BN * HD;
            const uint32_t* Vt = Vb + (size_t)(kt + 1) * BN * HD;
            #pragma unroll
            for (int i = 0; i < 8; i++) {
                int r = c_row + i * 8;
                cp16(smem_u32 + (nxt * KSTAGE + r * KSTRIDE + c_col) * 4, Kt + r * HD + c_col);
                cp16(smem_u32 + (SV_OFF + nxt * VSTAGE + r * VSTRIDE + c_col) * 4, Vt + r * HD + c_col);
            }
        }
        asm volatile("cp.async.commit_group;");
        asm volatile("cp.async.wait_group 1;");   // current stage complete
        __syncthreads();

        if (kt * BN <= row_max) {   // tile at/below this warp's diagonal
            const uint32_t* sK = sW + cur * KSTAGE;
            const uint32_t* sV = sW + SV_OFF + cur * VSTAGE;

            // ---- S = (Q*scale) K^T ----
            float s[8][4];
            #pragma unroll
            for (int j = 0; j < 8; j++) { s[j][0] = s[j][1] = s[j][2] = s[j][3] = 0.f; }
            #pragma unroll
            for (int j = 0; j < 8; j++) {
                const uint32_t* kr = sK + (j * 8 + g) * KSTRIDE;
                #pragma unroll
                for (int kc = 0; kc < 16; kc++) {
                    int d0 = kc * 8 + tg;
                    mma_tf32(s[j], qf[kc], kr[d0], kr[d0 + 4]);
                }
            }

            // ---- exact softcap -> log2 domain + causal mask ----
            const bool diag = (kt * BN + BN - 1 > row_min);
            #pragma unroll
            for (int j = 0; j < 8; j++) {
                #pragma unroll
                for (int q = 0; q < 4; q++) {
                    float z = fast_exp2(s[j][q] * TANH_ARG);
                    float x = fmaf(CAP_L2E_N2, fast_rcp(z + 1.0f), CAP_L2E);
                    if (diag) {
                        int col = kt * BN + j * 8 + tg * 2 + (q & 1);
                        int row = r0g + ((q >= 2) ? 8 : 0);
                        if (col > row) x = -1e9f;
                    }
                    s[j][q] = x;
                }
            }

            // ---- online softmax (log2 domain) ----
            float mx0 = -INFINITY, mx1 = -INFINITY;
            #pragma unroll
            for (int j = 0; j < 8; j++) {
                mx0 = fmaxf(mx0, fmaxf(s[j][0], s[j][1]));
                mx1 = fmaxf(mx1, fmaxf(s[j][2], s[j][3]));
            }
            mx0 = fmaxf(mx0, __shfl_xor_sync(0xffffffffu, mx0, 1));
            mx0 = fmaxf(mx0, __shfl_xor_sync(0xffffffffu, mx0, 2));
            mx1 = fmaxf(mx1, __shfl_xor_sync(0xffffffffu, mx1, 1));
            mx1 = fmaxf(mx1, __shfl_xor_sync(0xffffffffu, mx1, 2));

            float mn0 = fmaxf(m0, mx0), mn1 = fmaxf(m1, mx1);
            float a0 = fast_exp2(m0 - mn0);
            float a1 = fast_exp2(m1 - mn1);
            m0 = mn0; m1 = mn1;

            float sum0 = 0.f, sum1 = 0.f;
            #pragma unroll
            for (int j = 0; j < 8; j++) {
                s[j][0] = fast_exp2(s[j][0] - mn0);
                s[j][1] = fast_exp2(s[j][1] - mn0);
                s[j][2] = fast_exp2(s[j][2] - mn1);
                s[j][3] = fast_exp2(s[j][3] - mn1);
                sum0 += s[j][0] + s[j][1];
                sum1 += s[j][2] + s[j][3];
            }
            sum0 += __shfl_xor_sync(0xffffffffu, sum0, 1);
            sum0 += __shfl_xor_sync(0xffffffffu, sum0, 2);
            sum1 += __shfl_xor_sync(0xffffffffu, sum1, 1);
            sum1 += __shfl_xor_sync(0xffffffffu, sum1, 2);
            l0 = l0 * a0 + sum0;
            l1 = l1 * a1 + sum1;

            #pragma unroll
            for (int j = 0; j < 16; j++) {
                o[j][0] *= a0; o[j][1] *= a0; o[j][2] *= a1; o[j][3] *= a1;
            }

            // ---- O += P V ----
            const int src0 = (lane & 28) | (tg >> 1);
            const bool odd = tg & 1;
            #pragma unroll
            for (int kc = 0; kc < 8; kc++) {
                float v00 = __shfl_sync(0xffffffffu, s[kc][0], src0);
                float v01 = __shfl_sync(0xffffffffu, s[kc][1], src0);
                float v10 = __shfl_sync(0xffffffffu, s[kc][0], src0 + 2);
                float v11 = __shfl_sync(0xffffffffu, s[kc][1], src0 + 2);
                float w00 = __shfl_sync(0xffffffffu, s[kc][2], src0);
                float w01 = __shfl_sync(0xffffffffu, s[kc][3], src0);
                float w10 = __shfl_sync(0xffffffffu, s[kc][2], src0 + 2);
                float w11 = __shfl_sync(0xffffffffu, s[kc][3], src0 + 2);
                uint32_t pa[4];
                pa[0] = f2tf(odd ? v01 : v00);
                pa[1] = f2tf(odd ? w01 : w00);
                pa[2] = f2tf(odd ? v11 : v10);
                pa[3] = f2tf(odd ? w11 : w10);

                const uint32_t* vr0 = sV + (kc * 8 + tg) * VSTRIDE;
                const uint32_t* vr1 = sV + (kc * 8 + tg + 4) * VSTRIDE;
                #pragma unroll
                for (int jd = 0; jd < 16; jd++) {
                    int d0 = jd * 8 + g;
                    mma_tf32(o[jd], pa, vr0[d0], vr1[d0]);
                }
            }
        }
        __syncthreads();   // compute on this stage done before it is refilled next iter
    }

    // ---------------- epilogue: normalize + write [B, q, H*D] ----------------
    float inv0 = 1.f / l0, inv1 = 1.f / l1;
    float* Ob = Out + (size_t)b * SEQ * (NUM_HEADS * HD) + (size_t)h * HD;
    #pragma unroll
    for (int jd = 0; jd < 16; jd++) {
        int d0 = jd * 8 + tg * 2;
        float2 v0 = make_float2(o[jd][0] * inv0, o[jd][1] * inv0);
        float2 v1 = make_float2(o[jd][2] * inv1, o[jd][3] * inv1);
        *(float2*)(Ob + (size_t)r0g * (NUM_HEADS * HD) + d0)       = v0;
        *(float2*)(Ob + (size_t)(r0g + 8) * (NUM_HEADS * HD) + d0) = v1;
    }
}

extern "C" void kernel_launch(void* const* d_in, const int* in_sizes, int n_in,
                              void* d_out, int out_size)
{
    const float* Q = (const float*)d_in[0];
    const float* K = (const float*)d_in[1];
    const float* V = (const float*)d_in[2];
    float* Out = (float*)d_out;

    int B = in_sizes[0] / (NUM_HEADS * SEQ * HD);
    int nkv4 = (B * KV_HEADS * SEQ * HD) / 4;
    conv_kernel<<<(nkv4 + 255) / 256, 256>>>(K, V, nkv4);

    cudaFuncSetAttribute(fa_kernel, cudaFuncAttributeMaxDynamicSharedMemorySize, SMEM_TOTAL);
    dim3 grid(SEQ / BM, NUM_HEADS, B);
    fa_kernel<<<grid, NTHREADS, SMEM_TOTAL>>>(Q, Out);
}